// round 1
// baseline (speedup 1.0000x reference)
#include <cuda_runtime.h>
#include <math.h>

#define BB  4
#define NXX 512
#define NYY 512
#define DVV 32
#define KXX 64
#define KYY 64

#define PI_D 3.14159265358979323846

// Transform matrices (both orientations so smem staging is always a linear copy)
__device__ __align__(16) float g_Ct [NYY*KYY];   // Ct[n][k]  DCT-II fwd, k-minor
__device__ __align__(16) float g_Cr [KYY*NYY];   // C [k][n]  DCT (used for iDCT = C^T)
__device__ __align__(16) float g_Ftr[NXX*KXX];   // fwd rfft real, [n][k]
__device__ __align__(16) float g_Fti[NXX*KXX];   // fwd rfft imag, [n][k]
__device__ __align__(16) float g_Gr [KXX*NXX];   // inv rfft wt for Yr, [k][n]
__device__ __align__(16) float g_Gi [KXX*NXX];   // inv rfft wt for Yi, [k][n]

// Scratch
__device__ __align__(16) float g_S1 [(size_t)BB*NXX*KYY*DVV];  // [b][nx][ky][dv]
__device__ __align__(16) float g_S2r[(size_t)BB*KXX*KYY*DVV];  // [b][kx][ky][dv]
__device__ __align__(16) float g_S2i[(size_t)BB*KXX*KYY*DVV];
__device__ __align__(16) float g_S3r[(size_t)BB*KYY*KXX*DVV];  // [b][ky][kx][dv]
__device__ __align__(16) float g_S3i[(size_t)BB*KYY*KXX*DVV];
__device__ __align__(16) float g_S4 [(size_t)BB*NXX*KYY*DVV];  // [b][nx][ky][dv]

// ---------------------------------------------------------------------------
// Precompute transform matrices. fp64 trig with exact angle reduction.
// DCT-II ortho:  C[k][n] = s_k * cos(pi*k*(2n+1)/(2N)), s_0=sqrt(1/N), s_k=sqrt(2/N)
// rfft ortho:    F[k][n] = (cos th, -sin th)/sqrt(N), th = 2*pi*k*n/N
// irfft ortho (truncated, Hermitian): x[n] = sum_k c_k*(Fr*Yr + Fi*Yi), c_0=1,c_k=2
// (imag of bin 0 drops automatically since Fi[0][n] = 0, matching numpy c2r)
// ---------------------------------------------------------------------------
__global__ void k_precompute() {
    int idx = blockIdx.x * blockDim.x + threadIdx.x;
    if (idx >= KXX * NXX) return;
    int k = idx >> 9;
    int n = idx & 511;

    // DCT-II
    double sk = (k == 0) ? sqrt(1.0 / 512.0) : sqrt(2.0 / 512.0);
    int m = (k * (2 * n + 1)) & 2047;                  // period of cos(pi*m/1024)
    float Ckn = (float)(sk * cos(PI_D * (double)m / 1024.0));
    g_Cr[k * 512 + n] = Ckn;
    g_Ct[n * 64 + k]  = Ckn;

    // rfft
    int mm = (k * n) & 511;
    double ang = 2.0 * PI_D * (double)mm / 512.0;
    double isq = sqrt(1.0 / 512.0);
    float fr = (float)( cos(ang) * isq);
    float fi = (float)(-sin(ang) * isq);
    g_Ftr[n * 64 + k] = fr;
    g_Fti[n * 64 + k] = fi;
    float ck = (k == 0) ? 1.0f : 2.0f;
    g_Gr[k * 512 + n] = ck * fr;
    g_Gi[k * 512 + n] = ck * fi;
}

// ---------------------------------------------------------------------------
// Step 1: DCT-Y forward, truncated.  S1[b][nx][ky][dv] = sum_ny Ct[ny][ky]*x[b][nx][ny][dv]
// grid (NX, B), 128 threads, thread tile 4ky x 4dv
// ---------------------------------------------------------------------------
__global__ __launch_bounds__(128) void k_step1(const float* __restrict__ x) {
    __shared__ float As[64 * 64];   // [nn][ky]
    __shared__ float Bs[64 * 32];   // [nn][dv]
    int nx = blockIdx.x, b = blockIdx.y;
    int tid = threadIdx.x;
    int dg = tid & 7;               // dv0 = 4*dg
    int kg = tid >> 3;              // ky0 = 4*kg
    const float* xin = x + ((size_t)(b * NXX + nx)) * NYY * DVV;

    float acc[4][4] = {};
    for (int c = 0; c < 8; ++c) {
        const float4* sa = (const float4*)(g_Ct + c * 64 * 64);
        float4* da = (float4*)As;
#pragma unroll
        for (int t = 0; t < 8; ++t) da[tid + 128 * t] = sa[tid + 128 * t];
        const float4* sb = (const float4*)(xin + c * 64 * 32);
        float4* db = (float4*)Bs;
#pragma unroll
        for (int t = 0; t < 4; ++t) db[tid + 128 * t] = sb[tid + 128 * t];
        __syncthreads();
#pragma unroll 16
        for (int nn = 0; nn < 64; ++nn) {
            float4 a = *(const float4*)(As + nn * 64 + 4 * kg);
            float4 v = *(const float4*)(Bs + nn * 32 + 4 * dg);
            float av[4] = {a.x, a.y, a.z, a.w};
            float vv[4] = {v.x, v.y, v.z, v.w};
#pragma unroll
            for (int r = 0; r < 4; ++r)
#pragma unroll
                for (int q = 0; q < 4; ++q)
                    acc[r][q] = fmaf(av[r], vv[q], acc[r][q]);
        }
        __syncthreads();
    }
    float* out = g_S1 + ((size_t)(b * NXX + nx)) * KYY * DVV;
#pragma unroll
    for (int r = 0; r < 4; ++r)
        *(float4*)(out + (4 * kg + r) * 32 + 4 * dg) =
            make_float4(acc[r][0], acc[r][1], acc[r][2], acc[r][3]);
}

// ---------------------------------------------------------------------------
// Step 2: rFFT-X forward, truncated.
// S2r/i[b][kx][ky][dv] = sum_nx Ftr/Fti[nx][kx] * S1[b][nx][ky][dv]
// grid (KY, B), 128 threads, thread tile 4kx x 4dv (r+i)
// ---------------------------------------------------------------------------
__global__ __launch_bounds__(128) void k_step2() {
    __shared__ float Ar[32 * 64], Ai[32 * 64], Bs[32 * 32];
    int ky = blockIdx.x, b = blockIdx.y;
    int tid = threadIdx.x;
    int dg = tid & 7, kg = tid >> 3;
    const float* s1base = g_S1 + (size_t)b * NXX * KYY * DVV + (size_t)ky * DVV;

    float accr[4][4] = {}, acci[4][4] = {};
    for (int c = 0; c < 16; ++c) {
        const float4* sar = (const float4*)(g_Ftr + c * 32 * 64);
        const float4* sai = (const float4*)(g_Fti + c * 32 * 64);
#pragma unroll
        for (int t = 0; t < 4; ++t) {
            ((float4*)Ar)[tid + 128 * t] = sar[tid + 128 * t];
            ((float4*)Ai)[tid + 128 * t] = sai[tid + 128 * t];
        }
#pragma unroll
        for (int t = 0; t < 2; ++t) {
            int j = tid + 128 * t;
            int nn = j >> 3, q = j & 7;
            ((float4*)Bs)[j] =
                *(const float4*)(s1base + (size_t)(c * 32 + nn) * KYY * DVV + 4 * q);
        }
        __syncthreads();
#pragma unroll 8
        for (int nn = 0; nn < 32; ++nn) {
            float4 ar = *(const float4*)(Ar + nn * 64 + 4 * kg);
            float4 ai = *(const float4*)(Ai + nn * 64 + 4 * kg);
            float4 v  = *(const float4*)(Bs + nn * 32 + 4 * dg);
            float arr[4] = {ar.x, ar.y, ar.z, ar.w};
            float aii[4] = {ai.x, ai.y, ai.z, ai.w};
            float vv[4]  = {v.x, v.y, v.z, v.w};
#pragma unroll
            for (int r = 0; r < 4; ++r)
#pragma unroll
                for (int q = 0; q < 4; ++q) {
                    accr[r][q] = fmaf(arr[r], vv[q], accr[r][q]);
                    acci[r][q] = fmaf(aii[r], vv[q], acci[r][q]);
                }
        }
        __syncthreads();
    }
#pragma unroll
    for (int r = 0; r < 4; ++r) {
        int kx = 4 * kg + r;
        size_t dst = (((size_t)b * KXX + kx) * KYY + ky) * DVV + 4 * dg;
        *(float4*)(g_S2r + dst) = make_float4(accr[r][0], accr[r][1], accr[r][2], accr[r][3]);
        *(float4*)(g_S2i + dst) = make_float4(acci[r][0], acci[r][1], acci[r][2], acci[r][3]);
    }
}

// ---------------------------------------------------------------------------
// Step 3: per-mode complex channel mix. y[e,i,kx,ky] = sum_j R[i,j,kx,ky]*x[e,j,kx,ky]
// grid (KX, KY/16), 256 threads. R read in native layout (64B contiguous over ky).
// Output layout [b][ky][kx][i] (what step 4 wants contiguous).
// ---------------------------------------------------------------------------
__global__ __launch_bounds__(256) void k_step3(const float* __restrict__ Rr,
                                               const float* __restrict__ Ri) {
    __shared__ float Xr[4 * 16 * 33], Xi[4 * 16 * 33];  // [e][u][j], pitch 33
    __shared__ float Sr[4 * 32 * 16], Si[4 * 32 * 16];  // [i4][j][u]
    int kx = blockIdx.x, ky0 = blockIdx.y * 16;
    int tid = threadIdx.x;
    int lane = tid & 31, w = tid >> 5;

    // stage X (all e, 16 ky, 32 j)
#pragma unroll
    for (int r = 0; r < 8; ++r) {
        int row = w * 8 + r;
        int e = row >> 4, u = row & 15;
        size_t src = (((size_t)e * KXX + kx) * KYY + ky0 + u) * DVV + lane;
        Xr[(e * 16 + u) * 33 + lane] = g_S2r[src];
        Xi[(e * 16 + u) * 33 + lane] = g_S2i[src];
    }
    __syncthreads();

    int u = tid & 15, e = (tid >> 4) & 3, ii = tid >> 6;
    for (int ic = 0; ic < 8; ++ic) {
        // stage R for 4 output channels
#pragma unroll
        for (int t = 0; t < 8; ++t) {
            int flat = tid + 256 * t;
            int row = flat >> 4, uu = flat & 15;
            int i4 = row >> 5, j = row & 31;
            size_t src = (((size_t)(ic * 4 + i4) * DVV + j) * KXX + kx) * KYY + ky0 + uu;
            Sr[(i4 * 32 + j) * 16 + uu] = Rr[src];
            Si[(i4 * 32 + j) * 16 + uu] = Ri[src];
        }
        __syncthreads();
        float ar = 0.f, ai = 0.f;
#pragma unroll 8
        for (int j = 0; j < 32; ++j) {
            float xr = Xr[(e * 16 + u) * 33 + j];
            float xi = Xi[(e * 16 + u) * 33 + j];
            float rr = Sr[(ii * 32 + j) * 16 + u];
            float ri = Si[(ii * 32 + j) * 16 + u];
            ar = fmaf(rr, xr, ar);
            ar = fmaf(-ri, xi, ar);
            ai = fmaf(rr, xi, ai);
            ai = fmaf(ri, xr, ai);
        }
        int i = ic * 4 + ii;
        size_t dst = (((size_t)e * KYY + ky0 + u) * KXX + kx) * DVV + i;
        g_S3r[dst] = ar;
        g_S3i[dst] = ai;
        __syncthreads();
    }
}

// ---------------------------------------------------------------------------
// Step 4: irFFT-X truncated.
// S4[b][nx][ky][dv] = sum_kx Gr[kx][nx]*S3r + Gi[kx][nx]*S3i
// grid (NX/128, KY, B), 128 threads, thread tile 8nx x 4dv
// ---------------------------------------------------------------------------
__global__ __launch_bounds__(128) void k_step4() {
    __shared__ float Agr[32 * 128], Agi[32 * 128], Br[32 * 32], Bi[32 * 32];
    int nx0 = blockIdx.x * 128, ky = blockIdx.y, b = blockIdx.z;
    int tid = threadIdx.x;
    int dg = tid & 7, ng = tid >> 3;

    float acc[8][4] = {};
    for (int c = 0; c < 2; ++c) {
#pragma unroll
        for (int t = 0; t < 8; ++t) {
            int flat = tid + 128 * t;
            int row = flat >> 5, q = flat & 31;
            ((float4*)Agr)[flat] = *(const float4*)(g_Gr + (c * 32 + row) * 512 + nx0 + 4 * q);
            ((float4*)Agi)[flat] = *(const float4*)(g_Gi + (c * 32 + row) * 512 + nx0 + 4 * q);
        }
        const float4* sbr = (const float4*)(g_S3r + (((size_t)b * KYY + ky) * KXX + c * 32) * DVV);
        const float4* sbi = (const float4*)(g_S3i + (((size_t)b * KYY + ky) * KXX + c * 32) * DVV);
#pragma unroll
        for (int t = 0; t < 2; ++t) {
            ((float4*)Br)[tid + 128 * t] = sbr[tid + 128 * t];
            ((float4*)Bi)[tid + 128 * t] = sbi[tid + 128 * t];
        }
        __syncthreads();
#pragma unroll 4
        for (int kk = 0; kk < 32; ++kk) {
            float4 g0 = *(const float4*)(Agr + kk * 128 + 8 * ng);
            float4 g1 = *(const float4*)(Agr + kk * 128 + 8 * ng + 4);
            float4 h0 = *(const float4*)(Agi + kk * 128 + 8 * ng);
            float4 h1 = *(const float4*)(Agi + kk * 128 + 8 * ng + 4);
            float4 br = *(const float4*)(Br + kk * 32 + 4 * dg);
            float4 bi = *(const float4*)(Bi + kk * 32 + 4 * dg);
            float gg[8] = {g0.x, g0.y, g0.z, g0.w, g1.x, g1.y, g1.z, g1.w};
            float hh[8] = {h0.x, h0.y, h0.z, h0.w, h1.x, h1.y, h1.z, h1.w};
            float brr[4] = {br.x, br.y, br.z, br.w};
            float bii[4] = {bi.x, bi.y, bi.z, bi.w};
#pragma unroll
            for (int r = 0; r < 8; ++r)
#pragma unroll
                for (int q = 0; q < 4; ++q) {
                    acc[r][q] = fmaf(gg[r], brr[q], acc[r][q]);
                    acc[r][q] = fmaf(hh[r], bii[q], acc[r][q]);
                }
        }
        __syncthreads();
    }
#pragma unroll
    for (int r = 0; r < 8; ++r) {
        size_t dst = (((size_t)(b * NXX + nx0 + 8 * ng + r)) * KYY + ky) * DVV + 4 * dg;
        *(float4*)(g_S4 + dst) = make_float4(acc[r][0], acc[r][1], acc[r][2], acc[r][3]);
    }
}

// ---------------------------------------------------------------------------
// Step 5: iDCT-Y (DCT-III via C^T).
// out[b][nx][ny][dv] = sum_ky Cr[ky][ny] * S4[b][nx][ky][dv]
// grid (NY/128, NX, B), 128 threads, thread tile 8ny x 4dv
// ---------------------------------------------------------------------------
__global__ __launch_bounds__(128) void k_step5(float* __restrict__ out) {
    __shared__ float As[32 * 128], Bs[32 * 32];
    int ny0 = blockIdx.x * 128, nx = blockIdx.y, b = blockIdx.z;
    int tid = threadIdx.x;
    int dg = tid & 7, ng = tid >> 3;

    float acc[8][4] = {};
    for (int c = 0; c < 2; ++c) {
#pragma unroll
        for (int t = 0; t < 8; ++t) {
            int flat = tid + 128 * t;
            int row = flat >> 5, q = flat & 31;
            ((float4*)As)[flat] = *(const float4*)(g_Cr + (c * 32 + row) * 512 + ny0 + 4 * q);
        }
        const float4* sb = (const float4*)(g_S4 + ((size_t)(b * NXX + nx) * KYY + c * 32) * DVV);
#pragma unroll
        for (int t = 0; t < 2; ++t) ((float4*)Bs)[tid + 128 * t] = sb[tid + 128 * t];
        __syncthreads();
#pragma unroll 4
        for (int kk = 0; kk < 32; ++kk) {
            float4 a0 = *(const float4*)(As + kk * 128 + 8 * ng);
            float4 a1 = *(const float4*)(As + kk * 128 + 8 * ng + 4);
            float4 v  = *(const float4*)(Bs + kk * 32 + 4 * dg);
            float aa[8] = {a0.x, a0.y, a0.z, a0.w, a1.x, a1.y, a1.z, a1.w};
            float vv[4] = {v.x, v.y, v.z, v.w};
#pragma unroll
            for (int r = 0; r < 8; ++r)
#pragma unroll
                for (int q = 0; q < 4; ++q)
                    acc[r][q] = fmaf(aa[r], vv[q], acc[r][q]);
        }
        __syncthreads();
    }
#pragma unroll
    for (int r = 0; r < 8; ++r) {
        size_t dst = ((size_t)(b * NXX + nx) * NYY + ny0 + 8 * ng + r) * DVV + 4 * dg;
        *(float4*)(out + dst) = make_float4(acc[r][0], acc[r][1], acc[r][2], acc[r][3]);
    }
}

// ---------------------------------------------------------------------------
extern "C" void kernel_launch(void* const* d_in, const int* in_sizes, int n_in,
                              void* d_out, int out_size) {
    const float* x  = (const float*)d_in[0];
    const float* Rr = (const float*)d_in[1];
    const float* Ri = (const float*)d_in[2];
    float* out = (float*)d_out;

    k_precompute<<<128, 256>>>();
    k_step1<<<dim3(NXX, BB), 128>>>(x);
    k_step2<<<dim3(KYY, BB), 128>>>();
    k_step3<<<dim3(KXX, KYY / 16), 256>>>(Rr, Ri);
    k_step4<<<dim3(NXX / 128, KYY, BB), 128>>>();
    k_step5<<<dim3(NYY / 128, NXX, BB), 128>>>(out);
}